// round 12
// baseline (speedup 1.0000x reference)
#include <cuda_runtime.h>
#include <math_constants.h>

#define NG      121
#define NHAND   21
#define NPAIR   126   // 21*6
#define NOBJ    726   // 6*121
#define MAXB    8192

__device__ __align__(16) float2 g_acc[MAXB];   // (num, cnt) per batch
__device__ unsigned int g_sem = 0;             // returns to 0 at end of every launch

// g = yy - 2*zz. Must be bit-identical in phase B (min) and phase D (argmin match).
__device__ __forceinline__ float gval(float hx, float hy, float hz, float4 c)
{
    return fmaf(hx, c.x, fmaf(hy, c.y, fmaf(hz, c.z, c.w)));
}

__global__ __launch_bounds__(128, 13) void affinity_main(const float* __restrict__ poses,
                                                         float* __restrict__ out, int bs)
{
    const int b    = blockIdx.x;
    const int tid  = threadIdx.x;
    const int lane = tid & 31;
    const int warp = tid >> 5;
    const float* __restrict__ P = poses + b * 87;

    __shared__ float  s_pose[87];     // 21 hand + 8 obj, xyz
    __shared__ float  s_xx[NHAND];
    __shared__ float4 s_pts[NOBJ];    // (-2x, -2y, -2z, yy)
    __shared__ float  s_part[3*126];  // chunk partial minima [c][u][hh]
    __shared__ float  s_key[NPAIR];   // d2min = xx + gmin, flat = h*6+f
    __shared__ float  s_gb[NPAIR];    // exact gmin for argmin recovery
    __shared__ int    s_self[10];
    __shared__ float  s_seld[10];     // selected keys (d2min)
    __shared__ float4 s_cn[10];       // (m*nx, m*ny, m*nz, m)
    __shared__ float  s_geo[11];      // p1(3) dv(3) nd(3) dvn_e thr
    __shared__ float2 s_red[4];
    __shared__ int    s_flag;

    if (tid < 87) s_pose[tid] = P[tid];
    __syncthreads();

    if (tid < NHAND) {
        float x = s_pose[tid*3], y = s_pose[tid*3+1], z = s_pose[tid*3+2];
        s_xx[tid] = x*x + y*y + z*z;
    }

    const float* O = s_pose + NHAND*3;   // obj corners, 8 x 3

    // ---- Phase A: thread-per-gridpoint, 6 faces unrolled with literal corners ----
    if (tid < NG) {
        int iu = tid / 11;
        int iv = tid - iu * 11;
        float u = iu * 0.1f;
        float v = iv * 0.1f;
        float w0 = v * (1.0f - u);
        float w1 = v * u;
        float w2 = (1.0f - v) * (1.0f - u);
        float w3 = u * (1.0f - v);
        float Ox[8], Oy[8], Oz[8];
        #pragma unroll
        for (int k = 0; k < 8; k++) { Ox[k] = O[k*3]; Oy[k] = O[k*3+1]; Oz[k] = O[k*3+2]; }
        #define DOFACE(F, C0, C1, C2, C3) { \
            float x = w0*Ox[C0] + w1*Ox[C1] + w2*Ox[C2] + w3*Ox[C3]; \
            float y = w0*Oy[C0] + w1*Oy[C1] + w2*Oy[C2] + w3*Oy[C3]; \
            float z = w0*Oz[C0] + w1*Oz[C1] + w2*Oz[C2] + w3*Oz[C3]; \
            float yy = x*x + y*y + z*z; \
            s_pts[(F)*NG + tid] = make_float4(-2.0f*x, -2.0f*y, -2.0f*z, yy); }
        DOFACE(0, 0,1,2,3)
        DOFACE(1, 0,4,2,6)
        DOFACE(2, 0,1,4,5)
        DOFACE(3, 1,3,5,7)
        DOFACE(4, 2,3,6,7)
        DOFACE(5, 4,5,6,7)
        #undef DOFACE
    }
    __syncthreads();

    // ---- Phase B: each thread = (face, hand-triple, point-chunk).
    //      One LDS.128 per point amortized over 3 hands. ----
    if (tid < 126) {
        int c  = tid / 42;          // chunk 0..2
        int u  = tid - c * 42;      // unit 0..41
        int f  = u / 7;             // face 0..5
        int hg = u - f * 7;         // hand-group 0..6
        int h0 = hg * 3;

        float hx0 = s_pose[h0*3+0], hy0 = s_pose[h0*3+1], hz0 = s_pose[h0*3+2];
        float hx1 = s_pose[h0*3+3], hy1 = s_pose[h0*3+4], hz1 = s_pose[h0*3+5];
        float hx2 = s_pose[h0*3+6], hy2 = s_pose[h0*3+7], hz2 = s_pose[h0*3+8];

        const float4* __restrict__ q = s_pts + f * NG + c * 40;
        float m0 = CUDART_INF_F, m1 = CUDART_INF_F, m2 = CUDART_INF_F;
        #pragma unroll 10
        for (int p = 0; p < 40; p++) {
            float4 pt = q[p];
            m0 = fminf(m0, gval(hx0, hy0, hz0, pt));
            m1 = fminf(m1, gval(hx1, hy1, hz1, pt));
            m2 = fminf(m2, gval(hx2, hy2, hz2, pt));
        }
        if (c == 2) {               // point 120
            float4 pt = q[40];
            m0 = fminf(m0, gval(hx0, hy0, hz0, pt));
            m1 = fminf(m1, gval(hx1, hy1, hz1, pt));
            m2 = fminf(m2, gval(hx2, hy2, hz2, pt));
        }
        s_part[c*126 + u*3 + 0] = m0;
        s_part[c*126 + u*3 + 1] = m1;
        s_part[c*126 + u*3 + 2] = m2;
    }
    __syncthreads();

    // Combine chunk partials: flat pair index = h*6 + f (matches reference order)
    if (tid < NPAIR) {
        int h  = tid / 6;
        int f  = tid - h * 6;
        int hg = h / 3;
        int hh = h - hg * 3;
        int o  = (f*7 + hg)*3 + hh;
        float best = fminf(fminf(s_part[o], s_part[126 + o]), s_part[252 + o]);
        s_gb [tid] = best;                         // exact min of g (min is assoc/comm)
        s_key[tid] = __fadd_rn(s_xx[h], best);     // d2min (monotone in g)
    }
    __syncthreads();

    // ---- Phase C (warp 0): stable 10-smallest of the 126 keys
    //      Overlapped: warp 1 computes contact geometry into s_geo ----
    if (warp == 0) {
        float v0[4]; int i0[4];
        #pragma unroll
        for (int k = 0; k < 4; k++) {
            int t = tid + 32*k;
            if (t < NPAIR) { v0[k] = s_key[t]; i0[k] = t; }
            else           { v0[k] = CUDART_INF_F; i0[k] = 1 << 20; }
        }
        #pragma unroll
        for (int r = 0; r < 10; r++) {
            float bv = v0[0]; int bi = i0[0];
            #pragma unroll
            for (int k = 1; k < 4; k++)
                if (v0[k] < bv || (v0[k] == bv && i0[k] < bi)) { bv = v0[k]; bi = i0[k]; }
            #pragma unroll
            for (int off = 16; off; off >>= 1) {
                float ov = __shfl_xor_sync(0xffffffffu, bv, off);
                int   oi = __shfl_xor_sync(0xffffffffu, bi, off);
                if (ov < bv || (ov == bv && oi < bi)) { bv = ov; bi = oi; }
            }
            if (r == tid) { s_self[r] = bi; s_seld[r] = bv; }
            #pragma unroll
            for (int k = 0; k < 4; k++)
                if (i0[k] == bi) v0[k] = CUDART_INF_F;
        }
    } else if (warp == 1) {
        float p1x = (O[0]  + O[3]  + O[6]  + O[9] ) * 0.25f;
        float p1y = (O[1]  + O[4]  + O[7]  + O[10]) * 0.25f;
        float p1z = (O[2]  + O[5]  + O[8]  + O[11]) * 0.25f;
        float p2x = (O[12] + O[15] + O[18] + O[21]) * 0.25f;
        float p2y = (O[13] + O[16] + O[19] + O[22]) * 0.25f;
        float p2z = (O[14] + O[17] + O[20] + O[23]) * 0.25f;

        float l1 = 0.0f, l2 = 0.0f;
        #pragma unroll
        for (int e = 0; e < 4; e++) {
            int a = e, bb = (e + 1) & 3;
            float dx = O[a*3+0] - O[bb*3+0];
            float dy = O[a*3+1] - O[bb*3+1];
            float dz = O[a*3+2] - O[bb*3+2];
            l1 += sqrtf(dx*dx + dy*dy + dz*dz);
            int a2 = a + 4, b2 = bb + 4;
            dx = O[a2*3+0] - O[b2*3+0];
            dy = O[a2*3+1] - O[b2*3+1];
            dz = O[a2*3+2] - O[b2*3+2];
            l2 += sqrtf(dx*dx + dy*dy + dz*dz);
        }
        l1 *= 0.25f; l2 *= 0.25f;
        float thr = ((l1 + l2) * 0.5f) * 0.2f;

        float dvx = p2x - p1x, dvy = p2y - p1y, dvz = p2z - p1z;
        float dvn = sqrtf(dvx*dvx + dvy*dvy + dvz*dvz);
        float dvn_e = dvn + 1e-5f;

        if (lane == 0) {
            s_geo[0] = p1x; s_geo[1] = p1y; s_geo[2] = p1z;
            s_geo[3] = dvx; s_geo[4] = dvy; s_geo[5] = dvz;
            s_geo[6] = dvx / dvn_e; s_geo[7] = dvy / dvn_e; s_geo[8] = dvz / dvn_e;
            s_geo[9] = dvn_e; s_geo[10] = thr;
        }
    }
    __syncthreads();

    // ---- Phase D: argmin recovery by exact-match ballot + normal contribution ----
    {
        float p1x = s_geo[0], p1y = s_geo[1], p1z = s_geo[2];
        float dvx = s_geo[3], dvy = s_geo[4], dvz = s_geo[5];
        float ndx = s_geo[6], ndy = s_geo[7], ndz = s_geo[8];
        float dvn_e = s_geo[9], thr = s_geo[10];

        for (int c = warp; c < 10; c += 4) {
            int flat = s_self[c];
            int h = flat / 6;
            int f = flat - h * 6;
            float hx = s_pose[h*3], hy = s_pose[h*3+1], hz = s_pose[h*3+2];
            float gb = s_gb[flat];
            const float4* __restrict__ q = s_pts + f * NG;

            int p = 0;
            #pragma unroll
            for (int k = 0; k < 4; k++) {
                int pp = k*32 + lane;
                bool hit = (pp < NG) && (gval(hx, hy, hz, q[pp]) == gb);
                unsigned m = __ballot_sync(0xffffffffu, hit);
                if (m) { p = k*32 + (__ffs(m) - 1); break; }   // first occurrence
            }

            if (lane == 0) {
                float4 c4 = q[p];
                float cx = -0.5f * c4.x;   // exact recovery of coords
                float cy = -0.5f * c4.y;
                float cz = -0.5f * c4.z;
                float vx = cx - p1x, vy = cy - p1y, vz = cz - p1z;
                float inner = dvx*vx + dvy*vy + dvz*vz;
                float tt = inner / dvn_e;
                float rx = p1x + ndx * tt;
                float ry = p1y + ndy * tt;
                float rz = p1z + ndz * tt;
                float nx = cx - rx, ny = cy - ry, nz = cz - rz;
                float nn = sqrtf(nx*nx + ny*ny + nz*nz) + 1e-5f;
                nx /= nn; ny /= nn; nz /= nn;
                float dist = sqrtf(s_seld[c] + 1e-6f);
                float m = (dist < thr) ? 1.0f : 0.0f;
                s_cn[c] = make_float4(m*nx, m*ny, m*nz, m);
            }
        }
    }
    __syncthreads();

    // ---- Per-batch result: |sum m n|^2 and (sum m)^2 ----
    if (tid < 32) {
        float sx = 0.0f, sy = 0.0f, sz = 0.0f, sc = 0.0f;
        if (tid < 10) {
            float4 v = s_cn[tid];
            sx = v.x; sy = v.y; sz = v.z; sc = v.w;
        }
        #pragma unroll
        for (int off = 16; off; off >>= 1) {
            sx += __shfl_xor_sync(0xffffffffu, sx, off);
            sy += __shfl_xor_sync(0xffffffffu, sy, off);
            sz += __shfl_xor_sync(0xffffffffu, sz, off);
            sc += __shfl_xor_sync(0xffffffffu, sc, off);
        }
        if (tid == 0) {
            g_acc[b] = make_float2(sx*sx + sy*sy + sz*sz, sc*sc);
            __threadfence();                       // release g_acc[b]
            unsigned old = atomicAdd(&g_sem, 1u);
            s_flag = (old == (unsigned)(bs - 1));
        }
    }
    __syncthreads();

    // ---- Last block: deterministic final reduction, semaphore self-reset ----
    if (s_flag) {
        __threadfence();                           // acquire all g_acc
        float a = 0.0f, c = 0.0f;
        const float4* __restrict__ A = (const float4*)g_acc;
        int n4 = bs >> 1;
        for (int i = tid; i < n4; i += 128) {
            float4 v = A[i];
            a += v.x + v.z;
            c += v.y + v.w;
        }
        if ((bs & 1) && tid == 0) { float2 v = g_acc[bs - 1]; a += v.x; c += v.y; }
        #pragma unroll
        for (int off = 16; off; off >>= 1) {
            a += __shfl_xor_sync(0xffffffffu, a, off);
            c += __shfl_xor_sync(0xffffffffu, c, off);
        }
        if (lane == 0) s_red[warp] = make_float2(a, c);
        __syncthreads();
        if (tid == 0) {
            a = s_red[0].x + s_red[1].x + s_red[2].x + s_red[3].x;
            c = s_red[0].y + s_red[1].y + s_red[2].y + s_red[3].y;
            out[0] = a / (c + 1.0f);
            atomicExch(&g_sem, 0u);                // reset for next graph replay
        }
    }
}

extern "C" void kernel_launch(void* const* d_in, const int* in_sizes, int n_in,
                              void* d_out, int out_size)
{
    const float* poses = (const float*)d_in[0];
    int bs = in_sizes[0] / 87;
    if (bs > MAXB) bs = MAXB;
    affinity_main<<<bs, 128>>>(poses, (float*)d_out, bs);
}

// round 13
// speedup vs baseline: 1.0469x; 1.0469x over previous
#include <cuda_runtime.h>
#include <math_constants.h>

#define NG      121
#define NHAND   21
#define NPAIR   126   // 21*6
#define NOBJ    726   // 6*121
#define MAXB    8192

__device__ __align__(16) float2 g_acc[MAXB];   // (num, cnt) per batch
__device__ unsigned int g_sem = 0;             // returns to 0 at end of every launch

// g = yy - 2*zz. Must be bit-identical in phase B (min) and phase D (argmin match).
__device__ __forceinline__ float gval(float hx, float hy, float hz, float4 c)
{
    return fmaf(hx, c.x, fmaf(hy, c.y, fmaf(hz, c.z, c.w)));
}

__global__ __launch_bounds__(128, 12) void affinity_main(const float* __restrict__ poses,
                                                         float* __restrict__ out, int bs)
{
    const int b    = blockIdx.x;
    const int tid  = threadIdx.x;
    const int lane = tid & 31;
    const int warp = tid >> 5;
    const float* __restrict__ P = poses + b * 87;

    __shared__ float  s_pose[87];     // 21 hand + 8 obj, xyz
    __shared__ float  s_xx[NHAND];
    __shared__ float4 s_pts[NOBJ];    // (-2x, -2y, -2z, yy)
    __shared__ float  s_part[3*126];  // chunk partial minima [c][u][hh]
    __shared__ float  s_key[NPAIR];   // d2min = xx + gmin, flat = h*6+f
    __shared__ float  s_gb[NPAIR];    // exact gmin for argmin recovery
    __shared__ unsigned s_bal[4];     // per-warp mask ballots
    __shared__ int    s_self[10];
    __shared__ int    s_cnt;          // number of selected contacts (<=10)
    __shared__ int    s_fast;         // 1 = all selected are masked (m=1)
    __shared__ float4 s_cn[10];       // (m*nx, m*ny, m*nz, m)
    __shared__ float  s_geo[11];      // p1(3) dv(3) nd(3) dvn_e thr
    __shared__ float2 s_red[4];
    __shared__ int    s_flag;

    if (tid < 87) s_pose[tid] = P[tid];
    __syncthreads();

    if (tid < NHAND) {
        float x = s_pose[tid*3], y = s_pose[tid*3+1], z = s_pose[tid*3+2];
        s_xx[tid] = x*x + y*y + z*z;
    }

    const float* O = s_pose + NHAND*3;   // obj corners, 8 x 3

    // ---- Phase A: thread-per-gridpoint; tid 126 computes thr in parallel ----
    if (tid < NG) {
        int iu = tid / 11;
        int iv = tid - iu * 11;
        float u = iu * 0.1f;
        float v = iv * 0.1f;
        float w0 = v * (1.0f - u);
        float w1 = v * u;
        float w2 = (1.0f - v) * (1.0f - u);
        float w3 = u * (1.0f - v);
        float Ox[8], Oy[8], Oz[8];
        #pragma unroll
        for (int k = 0; k < 8; k++) { Ox[k] = O[k*3]; Oy[k] = O[k*3+1]; Oz[k] = O[k*3+2]; }
        #define DOFACE(F, C0, C1, C2, C3) { \
            float x = w0*Ox[C0] + w1*Ox[C1] + w2*Ox[C2] + w3*Ox[C3]; \
            float y = w0*Oy[C0] + w1*Oy[C1] + w2*Oy[C2] + w3*Oy[C3]; \
            float z = w0*Oz[C0] + w1*Oz[C1] + w2*Oz[C2] + w3*Oz[C3]; \
            float yy = x*x + y*y + z*z; \
            s_pts[(F)*NG + tid] = make_float4(-2.0f*x, -2.0f*y, -2.0f*z, yy); }
        DOFACE(0, 0,1,2,3)
        DOFACE(1, 0,4,2,6)
        DOFACE(2, 0,1,4,5)
        DOFACE(3, 1,3,5,7)
        DOFACE(4, 2,3,6,7)
        DOFACE(5, 4,5,6,7)
        #undef DOFACE
    } else if (tid == 126) {
        float l1 = 0.0f, l2 = 0.0f;
        #pragma unroll
        for (int e = 0; e < 4; e++) {
            int a = e, bb = (e + 1) & 3;
            float dx = O[a*3+0] - O[bb*3+0];
            float dy = O[a*3+1] - O[bb*3+1];
            float dz = O[a*3+2] - O[bb*3+2];
            l1 += sqrtf(dx*dx + dy*dy + dz*dz);
            int a2 = a + 4, b2 = bb + 4;
            dx = O[a2*3+0] - O[b2*3+0];
            dy = O[a2*3+1] - O[b2*3+1];
            dz = O[a2*3+2] - O[b2*3+2];
            l2 += sqrtf(dx*dx + dy*dy + dz*dz);
        }
        l1 *= 0.25f; l2 *= 0.25f;
        s_geo[10] = ((l1 + l2) * 0.5f) * 0.2f;   // thr
    }
    __syncthreads();

    // ---- Phase B: each thread = (face, hand-triple, point-chunk).
    //      One LDS.128 per point amortized over 3 hands. ----
    if (tid < 126) {
        int c  = tid / 42;          // chunk 0..2
        int u  = tid - c * 42;      // unit 0..41
        int f  = u / 7;             // face 0..5
        int hg = u - f * 7;         // hand-group 0..6
        int h0 = hg * 3;

        float hx0 = s_pose[h0*3+0], hy0 = s_pose[h0*3+1], hz0 = s_pose[h0*3+2];
        float hx1 = s_pose[h0*3+3], hy1 = s_pose[h0*3+4], hz1 = s_pose[h0*3+5];
        float hx2 = s_pose[h0*3+6], hy2 = s_pose[h0*3+7], hz2 = s_pose[h0*3+8];

        const float4* __restrict__ q = s_pts + f * NG + c * 40;
        float m0 = CUDART_INF_F, m1 = CUDART_INF_F, m2 = CUDART_INF_F;
        #pragma unroll 10
        for (int p = 0; p < 40; p++) {
            float4 pt = q[p];
            m0 = fminf(m0, gval(hx0, hy0, hz0, pt));
            m1 = fminf(m1, gval(hx1, hy1, hz1, pt));
            m2 = fminf(m2, gval(hx2, hy2, hz2, pt));
        }
        if (c == 2) {               // point 120
            float4 pt = q[40];
            m0 = fminf(m0, gval(hx0, hy0, hz0, pt));
            m1 = fminf(m1, gval(hx1, hy1, hz1, pt));
            m2 = fminf(m2, gval(hx2, hy2, hz2, pt));
        }
        s_part[c*126 + u*3 + 0] = m0;
        s_part[c*126 + u*3 + 1] = m1;
        s_part[c*126 + u*3 + 2] = m2;
    }
    __syncthreads();

    // ---- Combine chunk partials + mask ballot. flat = h*6+f ----
    {
        bool masked = false;
        if (tid < NPAIR) {
            int h  = tid / 6;
            int f  = tid - h * 6;
            int hg = h / 3;
            int hh = h - hg * 3;
            int o  = (f*7 + hg)*3 + hh;
            float best = fminf(fminf(s_part[o], s_part[126 + o]), s_part[252 + o]);
            float key  = __fadd_rn(s_xx[h], best);   // d2min (monotone in g)
            s_gb [tid] = best;                       // exact min of g
            s_key[tid] = key;
            masked = (sqrtf(key + 1e-6f) < s_geo[10]);  // identical chain to reference mask
        }
        unsigned bal = __ballot_sync(0xffffffffu, masked);
        if (lane == 0) s_bal[warp] = bal;
    }
    __syncthreads();

    // ---- Phase C (warp 0): if #masked <= 10 -> enumerate; else stable top-10.
    //      Overlapped: warp 1 computes contact geometry into s_geo[0..9] ----
    if (warp == 0) {
        int n = __popc(s_bal[0]) + __popc(s_bal[1]) + __popc(s_bal[2]) + __popc(s_bal[3]);
        if (n <= 10) {
            if (lane == 0) {
                int cnt = 0;
                #pragma unroll
                for (int w = 0; w < 4; w++) {
                    unsigned bal = s_bal[w];
                    while (bal) {
                        int l = __ffs(bal) - 1;
                        bal &= bal - 1;
                        s_self[cnt++] = w*32 + l;
                    }
                }
                s_cnt = n; s_fast = 1;
            }
        } else {
            float v0[4]; int i0[4];
            #pragma unroll
            for (int k = 0; k < 4; k++) {
                int t = lane + 32*k;
                if (t < NPAIR) { v0[k] = s_key[t]; i0[k] = t; }
                else           { v0[k] = CUDART_INF_F; i0[k] = 1 << 20; }
            }
            #pragma unroll
            for (int r = 0; r < 10; r++) {
                float bv = v0[0]; int bi = i0[0];
                #pragma unroll
                for (int k = 1; k < 4; k++)
                    if (v0[k] < bv || (v0[k] == bv && i0[k] < bi)) { bv = v0[k]; bi = i0[k]; }
                #pragma unroll
                for (int off = 16; off; off >>= 1) {
                    float ov = __shfl_xor_sync(0xffffffffu, bv, off);
                    int   oi = __shfl_xor_sync(0xffffffffu, bi, off);
                    if (ov < bv || (ov == bv && oi < bi)) { bv = ov; bi = oi; }
                }
                if (r == lane) s_self[r] = bi;
                #pragma unroll
                for (int k = 0; k < 4; k++)
                    if (i0[k] == bi) v0[k] = CUDART_INF_F;
            }
            if (lane == 0) { s_cnt = 10; s_fast = 0; }
        }
    } else if (warp == 1) {
        float p1x = (O[0]  + O[3]  + O[6]  + O[9] ) * 0.25f;
        float p1y = (O[1]  + O[4]  + O[7]  + O[10]) * 0.25f;
        float p1z = (O[2]  + O[5]  + O[8]  + O[11]) * 0.25f;
        float p2x = (O[12] + O[15] + O[18] + O[21]) * 0.25f;
        float p2y = (O[13] + O[16] + O[19] + O[22]) * 0.25f;
        float p2z = (O[14] + O[17] + O[20] + O[23]) * 0.25f;

        float dvx = p2x - p1x, dvy = p2y - p1y, dvz = p2z - p1z;
        float dvn = sqrtf(dvx*dvx + dvy*dvy + dvz*dvz);
        float dvn_e = dvn + 1e-5f;

        if (lane == 0) {
            s_geo[0] = p1x; s_geo[1] = p1y; s_geo[2] = p1z;
            s_geo[3] = dvx; s_geo[4] = dvy; s_geo[5] = dvz;
            s_geo[6] = dvx / dvn_e; s_geo[7] = dvy / dvn_e; s_geo[8] = dvz / dvn_e;
            s_geo[9] = dvn_e;
        }
    }
    __syncthreads();

    // ---- Phase D: argmin recovery by exact-match ballot + normal contribution ----
    {
        float p1x = s_geo[0], p1y = s_geo[1], p1z = s_geo[2];
        float dvx = s_geo[3], dvy = s_geo[4], dvz = s_geo[5];
        float ndx = s_geo[6], ndy = s_geo[7], ndz = s_geo[8];
        float dvn_e = s_geo[9], thr = s_geo[10];
        const int cnt  = s_cnt;
        const int fast = s_fast;

        for (int c = warp; c < cnt; c += 4) {
            int flat = s_self[c];
            int h = flat / 6;
            int f = flat - h * 6;
            float hx = s_pose[h*3], hy = s_pose[h*3+1], hz = s_pose[h*3+2];
            float gb = s_gb[flat];
            const float4* __restrict__ q = s_pts + f * NG;

            int p = 0;
            #pragma unroll
            for (int k = 0; k < 4; k++) {
                int pp = k*32 + lane;
                bool hit = (pp < NG) && (gval(hx, hy, hz, q[pp]) == gb);
                unsigned m = __ballot_sync(0xffffffffu, hit);
                if (m) { p = k*32 + (__ffs(m) - 1); break; }   // first occurrence
            }

            if (lane == 0) {
                float4 c4 = q[p];
                float cx = -0.5f * c4.x;   // exact recovery of coords
                float cy = -0.5f * c4.y;
                float cz = -0.5f * c4.z;
                float vx = cx - p1x, vy = cy - p1y, vz = cz - p1z;
                float inner = dvx*vx + dvy*vy + dvz*vz;
                float tt = inner / dvn_e;
                float rx = p1x + ndx * tt;
                float ry = p1y + ndy * tt;
                float rz = p1z + ndz * tt;
                float nx = cx - rx, ny = cy - ry, nz = cz - rz;
                float nn = sqrtf(nx*nx + ny*ny + nz*nz) + 1e-5f;
                nx /= nn; ny /= nn; nz /= nn;
                float m = 1.0f;
                if (!fast) {
                    float dist = sqrtf(s_key[flat] + 1e-6f);
                    m = (dist < thr) ? 1.0f : 0.0f;
                }
                s_cn[c] = make_float4(m*nx, m*ny, m*nz, m);
            }
        }
    }
    __syncthreads();

    // ---- Per-batch result: |sum m n|^2 and (sum m)^2 ----
    if (tid < 32) {
        float sx = 0.0f, sy = 0.0f, sz = 0.0f, sc = 0.0f;
        if (tid < s_cnt) {
            float4 v = s_cn[tid];
            sx = v.x; sy = v.y; sz = v.z; sc = v.w;
        }
        #pragma unroll
        for (int off = 16; off; off >>= 1) {
            sx += __shfl_xor_sync(0xffffffffu, sx, off);
            sy += __shfl_xor_sync(0xffffffffu, sy, off);
            sz += __shfl_xor_sync(0xffffffffu, sz, off);
            sc += __shfl_xor_sync(0xffffffffu, sc, off);
        }
        if (tid == 0) {
            g_acc[b] = make_float2(sx*sx + sy*sy + sz*sz, sc*sc);
            __threadfence();                       // release g_acc[b]
            unsigned old = atomicAdd(&g_sem, 1u);
            s_flag = (old == (unsigned)(bs - 1));
        }
    }
    __syncthreads();

    // ---- Last block: deterministic final reduction, semaphore self-reset ----
    if (s_flag) {
        __threadfence();                           // acquire all g_acc
        float a = 0.0f, c = 0.0f;
        const float4* __restrict__ A = (const float4*)g_acc;
        int n4 = bs >> 1;
        for (int i = tid; i < n4; i += 128) {
            float4 v = A[i];
            a += v.x + v.z;
            c += v.y + v.w;
        }
        if ((bs & 1) && tid == 0) { float2 v = g_acc[bs - 1]; a += v.x; c += v.y; }
        #pragma unroll
        for (int off = 16; off; off >>= 1) {
            a += __shfl_xor_sync(0xffffffffu, a, off);
            c += __shfl_xor_sync(0xffffffffu, c, off);
        }
        if (lane == 0) s_red[warp] = make_float2(a, c);
        __syncthreads();
        if (tid == 0) {
            a = s_red[0].x + s_red[1].x + s_red[2].x + s_red[3].x;
            c = s_red[0].y + s_red[1].y + s_red[2].y + s_red[3].y;
            out[0] = a / (c + 1.0f);
            atomicExch(&g_sem, 0u);                // reset for next graph replay
        }
    }
}

extern "C" void kernel_launch(void* const* d_in, const int* in_sizes, int n_in,
                              void* d_out, int out_size)
{
    const float* poses = (const float*)d_in[0];
    int bs = in_sizes[0] / 87;
    if (bs > MAXB) bs = MAXB;
    affinity_main<<<bs, 128>>>(poses, (float*)d_out, bs);
}

// round 14
// speedup vs baseline: 1.4203x; 1.3567x over previous
#include <cuda_runtime.h>
#include <math_constants.h>

#define NG      121
#define NHAND   21
#define NPAIR   126   // 21*6
#define NOBJ    726   // 6*121
#define MAXB    8192

__constant__ int c_face[6][4] = {
    {0,1,2,3},{0,4,2,6},{0,1,4,5},{1,3,5,7},{2,3,6,7},{4,5,6,7}
};

__device__ __align__(16) float2 g_acc[MAXB];   // (num, cnt) per batch
__device__ unsigned int g_sem = 0;             // returns to 0 at end of every launch

// g = yy - 2*zz, evaluated with the same fma chain as always (reference-consistent value).
__device__ __forceinline__ float gval(float hx, float hy, float hz, float4 c)
{
    return fmaf(hx, c.x, fmaf(hy, c.y, fmaf(hz, c.z, c.w)));
}

__global__ __launch_bounds__(128, 12) void affinity_main(const float* __restrict__ poses,
                                                         float* __restrict__ out, int bs)
{
    const int b    = blockIdx.x;
    const int tid  = threadIdx.x;
    const int lane = tid & 31;
    const int warp = tid >> 5;
    const float* __restrict__ P = poses + b * 87;

    __shared__ float  s_pose[87];     // 21 hand + 8 obj, xyz
    __shared__ float  s_xx[NHAND];
    __shared__ float4 s_pts[NOBJ];    // (-2x, -2y, -2z, yy)
    __shared__ float  s_co[6*12];     // per face: a(3) b(3) c(3) e(3); point=a+bu+cv+euv
    __shared__ float  s_key[NPAIR];   // d2min = xx + g(chosen), flat = h*6+f
    __shared__ int    s_argp[NPAIR];  // chosen grid index p (0..120)
    __shared__ unsigned s_bal[4];     // per-warp mask ballots
    __shared__ int    s_self[10];
    __shared__ int    s_cnt;          // number of selected contacts (<=10)
    __shared__ int    s_fast;         // 1 = all selected are masked (m=1)
    __shared__ float4 s_cn[10];       // (m*nx, m*ny, m*nz, m)
    __shared__ float  s_geo[11];      // p1(3) dv(3) nd(3) dvn_e thr
    __shared__ float2 s_red[4];
    __shared__ int    s_flag;

    if (tid < 87) s_pose[tid] = P[tid];
    __syncthreads();

    if (tid < NHAND) {
        float x = s_pose[tid*3], y = s_pose[tid*3+1], z = s_pose[tid*3+2];
        s_xx[tid] = x*x + y*y + z*z;
    }

    const float* O = s_pose + NHAND*3;   // obj corners, 8 x 3

    // ---- Phase A: grid points (tid<121), face coeffs (tid 121..126), thr (tid 127) ----
    if (tid < NG) {
        int iu = tid / 11;
        int iv = tid - iu * 11;
        float u = iu * 0.1f;
        float v = iv * 0.1f;
        float w0 = v * (1.0f - u);
        float w1 = v * u;
        float w2 = (1.0f - v) * (1.0f - u);
        float w3 = u * (1.0f - v);
        float Ox[8], Oy[8], Oz[8];
        #pragma unroll
        for (int k = 0; k < 8; k++) { Ox[k] = O[k*3]; Oy[k] = O[k*3+1]; Oz[k] = O[k*3+2]; }
        #define DOFACE(F, C0, C1, C2, C3) { \
            float x = w0*Ox[C0] + w1*Ox[C1] + w2*Ox[C2] + w3*Ox[C3]; \
            float y = w0*Oy[C0] + w1*Oy[C1] + w2*Oy[C2] + w3*Oy[C3]; \
            float z = w0*Oz[C0] + w1*Oz[C1] + w2*Oz[C2] + w3*Oz[C3]; \
            float yy = x*x + y*y + z*z; \
            s_pts[(F)*NG + tid] = make_float4(-2.0f*x, -2.0f*y, -2.0f*z, yy); }
        DOFACE(0, 0,1,2,3)
        DOFACE(1, 0,4,2,6)
        DOFACE(2, 0,1,4,5)
        DOFACE(3, 1,3,5,7)
        DOFACE(4, 2,3,6,7)
        DOFACE(5, 4,5,6,7)
        #undef DOFACE
    } else if (tid < 127) {
        // point(u,v) = a + b u + c v + e uv ;  a=C2, b=C3-C2, c=C0-C2, e=C1-C0-C3+C2
        int f = tid - 121;
        int c0 = c_face[f][0], c1 = c_face[f][1], c2 = c_face[f][2], c3 = c_face[f][3];
        float* co = s_co + f*12;
        #pragma unroll
        for (int d = 0; d < 3; d++) {
            float A0 = O[c0*3+d], A1 = O[c1*3+d], A2 = O[c2*3+d], A3 = O[c3*3+d];
            co[0+d] = A2;
            co[3+d] = A3 - A2;
            co[6+d] = A0 - A2;
            co[9+d] = (A1 - A0) - (A3 - A2);
        }
    } else {
        float l1 = 0.0f, l2 = 0.0f;
        #pragma unroll
        for (int e = 0; e < 4; e++) {
            int a = e, bb = (e + 1) & 3;
            float dx = O[a*3+0] - O[bb*3+0];
            float dy = O[a*3+1] - O[bb*3+1];
            float dz = O[a*3+2] - O[bb*3+2];
            l1 += sqrtf(dx*dx + dy*dy + dz*dz);
            int a2 = a + 4, b2 = bb + 4;
            dx = O[a2*3+0] - O[b2*3+0];
            dy = O[a2*3+1] - O[b2*3+1];
            dz = O[a2*3+2] - O[b2*3+2];
            l2 += sqrtf(dx*dx + dy*dy + dz*dz);
        }
        l1 *= 0.25f; l2 *= 0.25f;
        s_geo[10] = ((l1 + l2) * 0.5f) * 0.2f;   // thr
    }
    __syncthreads();

    // ---- Phase B: thread = (face, hand). Per u-row, the quadratic in v is convex
    //      (C=|B|^2>=0); pick the vertex-rounded grid point and evaluate it with the
    //      reference-exact gval chain. 11 candidates instead of 121 evaluations. ----
    if (tid < NPAIR) {
        int f = tid / NHAND;        // lanes grouped by face -> broadcast coeff loads
        int h = tid - f * NHAND;
        float hx = s_pose[h*3], hy = s_pose[h*3+1], hz = s_pose[h*3+2];
        const float* co = s_co + f*12;
        float qx = co[0] - hx, qy = co[1] - hy, qz = co[2] - hz;
        float bx = co[3], by = co[4], bz = co[5];
        float cx = co[6], cy = co[7], cz = co[8];
        float ex = co[9], ey = co[10], ez = co[11];
        const float4* __restrict__ q = s_pts + f * NG;

        float best = CUDART_INF_F;
        int   bp   = 0;
        #pragma unroll
        for (int iu = 0; iu < 11; iu++) {
            float u  = iu * 0.1f;
            float Ax = fmaf(bx, u, qx), Ay = fmaf(by, u, qy), Az = fmaf(bz, u, qz);
            float Bx = fmaf(ex, u, cx), By = fmaf(ey, u, cy), Bz = fmaf(ez, u, cz);
            float m  = Ax*Bx + Ay*By + Az*Bz;
            float C  = Bx*Bx + By*By + Bz*Bz;
            float t  = __fdividef(-10.0f * m, C);   // NaN/inf -> F2I saturates/0, then clamp
            int  iv  = __float2int_rn(t);
            iv = iv < 0 ? 0 : (iv > 10 ? 10 : iv);
            int  p   = iu*11 + iv;
            float g  = gval(hx, hy, hz, q[p]);
            if (g < best) { best = g; bp = p; }     // first row (ascending iu) wins ties
        }
        s_key [h*6 + f] = __fadd_rn(s_xx[h], best);
        s_argp[h*6 + f] = bp;
    }
    __syncthreads();

    // ---- Mask ballot in flat order ----
    {
        bool masked = (tid < NPAIR) && (sqrtf(s_key[tid] + 1e-6f) < s_geo[10]);
        unsigned bal = __ballot_sync(0xffffffffu, masked);
        if (lane == 0) s_bal[warp] = bal;
    }
    __syncthreads();

    // ---- Phase C (warp 0): if #masked <= 10 -> enumerate; else stable top-10.
    //      Overlapped: warp 1 computes contact geometry into s_geo[0..9] ----
    if (warp == 0) {
        int n = __popc(s_bal[0]) + __popc(s_bal[1]) + __popc(s_bal[2]) + __popc(s_bal[3]);
        if (n <= 10) {
            if (lane == 0) {
                int cnt = 0;
                #pragma unroll
                for (int w = 0; w < 4; w++) {
                    unsigned bal = s_bal[w];
                    while (bal) {
                        int l = __ffs(bal) - 1;
                        bal &= bal - 1;
                        s_self[cnt++] = w*32 + l;
                    }
                }
                s_cnt = n; s_fast = 1;
            }
        } else {
            float v0[4]; int i0[4];
            #pragma unroll
            for (int k = 0; k < 4; k++) {
                int t = lane + 32*k;
                if (t < NPAIR) { v0[k] = s_key[t]; i0[k] = t; }
                else           { v0[k] = CUDART_INF_F; i0[k] = 1 << 20; }
            }
            #pragma unroll
            for (int r = 0; r < 10; r++) {
                float bv = v0[0]; int bi = i0[0];
                #pragma unroll
                for (int k = 1; k < 4; k++)
                    if (v0[k] < bv || (v0[k] == bv && i0[k] < bi)) { bv = v0[k]; bi = i0[k]; }
                #pragma unroll
                for (int off = 16; off; off >>= 1) {
                    float ov = __shfl_xor_sync(0xffffffffu, bv, off);
                    int   oi = __shfl_xor_sync(0xffffffffu, bi, off);
                    if (ov < bv || (ov == bv && oi < bi)) { bv = ov; bi = oi; }
                }
                if (r == lane) s_self[r] = bi;
                #pragma unroll
                for (int k = 0; k < 4; k++)
                    if (i0[k] == bi) v0[k] = CUDART_INF_F;
            }
            if (lane == 0) { s_cnt = 10; s_fast = 0; }
        }
    } else if (warp == 1) {
        float p1x = (O[0]  + O[3]  + O[6]  + O[9] ) * 0.25f;
        float p1y = (O[1]  + O[4]  + O[7]  + O[10]) * 0.25f;
        float p1z = (O[2]  + O[5]  + O[8]  + O[11]) * 0.25f;
        float p2x = (O[12] + O[15] + O[18] + O[21]) * 0.25f;
        float p2y = (O[13] + O[16] + O[19] + O[22]) * 0.25f;
        float p2z = (O[14] + O[17] + O[20] + O[23]) * 0.25f;

        float dvx = p2x - p1x, dvy = p2y - p1y, dvz = p2z - p1z;
        float dvn = sqrtf(dvx*dvx + dvy*dvy + dvz*dvz);
        float dvn_e = dvn + 1e-5f;

        if (lane == 0) {
            s_geo[0] = p1x; s_geo[1] = p1y; s_geo[2] = p1z;
            s_geo[3] = dvx; s_geo[4] = dvy; s_geo[5] = dvz;
            s_geo[6] = dvx / dvn_e; s_geo[7] = dvy / dvn_e; s_geo[8] = dvz / dvn_e;
            s_geo[9] = dvn_e;
        }
    }
    __syncthreads();

    // ---- Phase D: one thread per contact (argmin index already known) ----
    if (tid < s_cnt) {
        float p1x = s_geo[0], p1y = s_geo[1], p1z = s_geo[2];
        float dvx = s_geo[3], dvy = s_geo[4], dvz = s_geo[5];
        float ndx = s_geo[6], ndy = s_geo[7], ndz = s_geo[8];
        float dvn_e = s_geo[9], thr = s_geo[10];

        int flat = s_self[tid];
        int h = flat / 6;
        int f = flat - h * 6;
        (void)h;
        float4 c4 = s_pts[f * NG + s_argp[flat]];
        float cx = -0.5f * c4.x;   // exact recovery of coords
        float cy = -0.5f * c4.y;
        float cz = -0.5f * c4.z;
        float vx = cx - p1x, vy = cy - p1y, vz = cz - p1z;
        float inner = dvx*vx + dvy*vy + dvz*vz;
        float tt = inner / dvn_e;
        float rx = p1x + ndx * tt;
        float ry = p1y + ndy * tt;
        float rz = p1z + ndz * tt;
        float nx = cx - rx, ny = cy - ry, nz = cz - rz;
        float nn = sqrtf(nx*nx + ny*ny + nz*nz) + 1e-5f;
        nx /= nn; ny /= nn; nz /= nn;
        float m = 1.0f;
        if (!s_fast) {
            float dist = sqrtf(s_key[flat] + 1e-6f);
            m = (dist < thr) ? 1.0f : 0.0f;
        }
        s_cn[tid] = make_float4(m*nx, m*ny, m*nz, m);
    }
    __syncthreads();

    // ---- Per-batch result: |sum m n|^2 and (sum m)^2 ----
    if (tid < 32) {
        float sx = 0.0f, sy = 0.0f, sz = 0.0f, sc = 0.0f;
        if (tid < s_cnt) {
            float4 v = s_cn[tid];
            sx = v.x; sy = v.y; sz = v.z; sc = v.w;
        }
        #pragma unroll
        for (int off = 16; off; off >>= 1) {
            sx += __shfl_xor_sync(0xffffffffu, sx, off);
            sy += __shfl_xor_sync(0xffffffffu, sy, off);
            sz += __shfl_xor_sync(0xffffffffu, sz, off);
            sc += __shfl_xor_sync(0xffffffffu, sc, off);
        }
        if (tid == 0) {
            g_acc[b] = make_float2(sx*sx + sy*sy + sz*sz, sc*sc);
            __threadfence();                       // release g_acc[b]
            unsigned old = atomicAdd(&g_sem, 1u);
            s_flag = (old == (unsigned)(bs - 1));
        }
    }
    __syncthreads();

    // ---- Last block: deterministic final reduction, semaphore self-reset ----
    if (s_flag) {
        __threadfence();                           // acquire all g_acc
        float a = 0.0f, c = 0.0f;
        const float4* __restrict__ A = (const float4*)g_acc;
        int n4 = bs >> 1;
        for (int i = tid; i < n4; i += 128) {
            float4 v = A[i];
            a += v.x + v.z;
            c += v.y + v.w;
        }
        if ((bs & 1) && tid == 0) { float2 v = g_acc[bs - 1]; a += v.x; c += v.y; }
        #pragma unroll
        for (int off = 16; off; off >>= 1) {
            a += __shfl_xor_sync(0xffffffffu, a, off);
            c += __shfl_xor_sync(0xffffffffu, c, off);
        }
        if (lane == 0) s_red[warp] = make_float2(a, c);
        __syncthreads();
        if (tid == 0) {
            a = s_red[0].x + s_red[1].x + s_red[2].x + s_red[3].x;
            c = s_red[0].y + s_red[1].y + s_red[2].y + s_red[3].y;
            out[0] = a / (c + 1.0f);
            atomicExch(&g_sem, 0u);                // reset for next graph replay
        }
    }
}

extern "C" void kernel_launch(void* const* d_in, const int* in_sizes, int n_in,
                              void* d_out, int out_size)
{
    const float* poses = (const float*)d_in[0];
    int bs = in_sizes[0] / 87;
    if (bs > MAXB) bs = MAXB;
    affinity_main<<<bs, 128>>>(poses, (float*)d_out, bs);
}

// round 15
// speedup vs baseline: 1.5784x; 1.1113x over previous
#include <cuda_runtime.h>
#include <math_constants.h>

#define NHAND   21
#define NPAIR   126   // 21*6
#define MAXB    8192

__constant__ int c_face[6][4] = {
    {0,1,2,3},{0,4,2,6},{0,1,4,5},{1,3,5,7},{2,3,6,7},{4,5,6,7}
};

__device__ __align__(16) float2 g_acc[MAXB];   // (num, cnt) per batch
__device__ unsigned int g_sem = 0;             // returns to 0 at end of every launch

__global__ __launch_bounds__(128, 12) void affinity_main(const float* __restrict__ poses,
                                                         float* __restrict__ out, int bs)
{
    const int b    = blockIdx.x;
    const int tid  = threadIdx.x;
    const int lane = tid & 31;
    const int warp = tid >> 5;
    const float* __restrict__ P = poses + b * 87;

    __shared__ float  s_pose[87];     // 21 hand + 8 obj, xyz
    __shared__ float  s_co[6*12];     // per face: a(3) b(3) c(3) e(3); point=a+bu+cv+euv
    __shared__ float  s_key[NPAIR];   // d2min, flat = h*6+f
    __shared__ int    s_argp[NPAIR];  // chosen grid index p = iu*11+iv
    __shared__ unsigned s_bal[4];     // per-warp mask ballots
    __shared__ int    s_self[10];
    __shared__ int    s_cnt;          // number of selected contacts (<=10)
    __shared__ int    s_fast;         // 1 = all selected are masked (m=1)
    __shared__ float4 s_cn[10];       // (m*nx, m*ny, m*nz, m)
    __shared__ float  s_geo[11];      // p1(3) dv(3) nd(3) dvn_e thr
    __shared__ float2 s_red[4];
    __shared__ int    s_flag;

    // ---- Stage pose; coeff/thr threads read corners straight from global (one sync) ----
    if (tid < 87) {
        s_pose[tid] = P[tid];
    } else if (tid >= 121 && tid < 127) {
        // point(u,v) = a + b u + c v + e uv ;  a=C2, b=C3-C2, c=C0-C2, e=(C1-C0)-(C3-C2)
        int f = tid - 121;
        int c0 = c_face[f][0], c1 = c_face[f][1], c2 = c_face[f][2], c3 = c_face[f][3];
        const float* Og = P + NHAND*3;
        float* co = s_co + f*12;
        #pragma unroll
        for (int d = 0; d < 3; d++) {
            float A0 = Og[c0*3+d], A1 = Og[c1*3+d], A2 = Og[c2*3+d], A3 = Og[c3*3+d];
            co[0+d] = A2;
            co[3+d] = A3 - A2;
            co[6+d] = A0 - A2;
            co[9+d] = (A1 - A0) - (A3 - A2);
        }
    } else if (tid == 127) {
        const float* Og = P + NHAND*3;
        float l1 = 0.0f, l2 = 0.0f;
        #pragma unroll
        for (int e = 0; e < 4; e++) {
            int a = e, bb = (e + 1) & 3;
            float dx = Og[a*3+0] - Og[bb*3+0];
            float dy = Og[a*3+1] - Og[bb*3+1];
            float dz = Og[a*3+2] - Og[bb*3+2];
            l1 += sqrtf(dx*dx + dy*dy + dz*dz);
            int a2 = a + 4, b2 = bb + 4;
            dx = Og[a2*3+0] - Og[b2*3+0];
            dy = Og[a2*3+1] - Og[b2*3+1];
            dz = Og[a2*3+2] - Og[b2*3+2];
            l2 += sqrtf(dx*dx + dy*dy + dz*dz);
        }
        l1 *= 0.25f; l2 *= 0.25f;
        s_geo[10] = ((l1 + l2) * 0.5f) * 0.2f;   // thr
    }
    __syncthreads();

    // ---- Phase B: thread = (face, hand). Per u-row the quadratic in v is convex;
    //      take the vertex-rounded grid point, evaluate d2 = |q + b u + B v|^2 directly. ----
    if (tid < NPAIR) {
        int f = tid / NHAND;        // lanes grouped by face -> broadcast coeff loads
        int h = tid - f * NHAND;
        float hx = s_pose[h*3], hy = s_pose[h*3+1], hz = s_pose[h*3+2];
        const float* co = s_co + f*12;
        float qx = co[0] - hx, qy = co[1] - hy, qz = co[2] - hz;
        float bx = co[3], by = co[4], bz = co[5];
        float cx = co[6], cy = co[7], cz = co[8];
        float ex = co[9], ey = co[10], ez = co[11];

        float best = CUDART_INF_F;
        int   bp   = 0;
        #pragma unroll
        for (int iu = 0; iu < 11; iu++) {
            float u  = iu * 0.1f;
            float Ax = fmaf(bx, u, qx), Ay = fmaf(by, u, qy), Az = fmaf(bz, u, qz);
            float Bx = fmaf(ex, u, cx), By = fmaf(ey, u, cy), Bz = fmaf(ez, u, cz);
            float m  = Ax*Bx + Ay*By + Az*Bz;
            float C  = Bx*Bx + By*By + Bz*Bz;
            float t  = __fdividef(-10.0f * m, C);   // NaN/inf -> F2I 0/sat, then clamp
            int  iv  = __float2int_rn(t);
            iv = iv < 0 ? 0 : (iv > 10 ? 10 : iv);
            float v  = iv * 0.1f;
            float Wx = fmaf(Bx, v, Ax), Wy = fmaf(By, v, Ay), Wz = fmaf(Bz, v, Az);
            float d2 = Wx*Wx + Wy*Wy + Wz*Wz;
            if (d2 < best) { best = d2; bp = iu*11 + iv; }
        }
        s_key [h*6 + f] = best;
        s_argp[h*6 + f] = bp;
    }
    __syncthreads();

    // ---- Mask ballot in flat order ----
    {
        bool masked = (tid < NPAIR) && (sqrtf(s_key[tid] + 1e-6f) < s_geo[10]);
        unsigned bal = __ballot_sync(0xffffffffu, masked);
        if (lane == 0) s_bal[warp] = bal;
    }
    __syncthreads();

    // ---- Phase C (warp 0): if #masked <= 10 -> enumerate; else stable top-10.
    //      Overlapped: warp 1 computes contact geometry into s_geo[0..9] ----
    if (warp == 0) {
        int n = __popc(s_bal[0]) + __popc(s_bal[1]) + __popc(s_bal[2]) + __popc(s_bal[3]);
        if (n <= 10) {
            if (lane == 0) {
                int cnt = 0;
                #pragma unroll
                for (int w = 0; w < 4; w++) {
                    unsigned bal = s_bal[w];
                    while (bal) {
                        int l = __ffs(bal) - 1;
                        bal &= bal - 1;
                        s_self[cnt++] = w*32 + l;
                    }
                }
                s_cnt = n; s_fast = 1;
            }
        } else {
            float v0[4]; int i0[4];
            #pragma unroll
            for (int k = 0; k < 4; k++) {
                int t = lane + 32*k;
                if (t < NPAIR) { v0[k] = s_key[t]; i0[k] = t; }
                else           { v0[k] = CUDART_INF_F; i0[k] = 1 << 20; }
            }
            #pragma unroll
            for (int r = 0; r < 10; r++) {
                float bv = v0[0]; int bi = i0[0];
                #pragma unroll
                for (int k = 1; k < 4; k++)
                    if (v0[k] < bv || (v0[k] == bv && i0[k] < bi)) { bv = v0[k]; bi = i0[k]; }
                #pragma unroll
                for (int off = 16; off; off >>= 1) {
                    float ov = __shfl_xor_sync(0xffffffffu, bv, off);
                    int   oi = __shfl_xor_sync(0xffffffffu, bi, off);
                    if (ov < bv || (ov == bv && oi < bi)) { bv = ov; bi = oi; }
                }
                if (r == lane) s_self[r] = bi;
                #pragma unroll
                for (int k = 0; k < 4; k++)
                    if (i0[k] == bi) v0[k] = CUDART_INF_F;
            }
            if (lane == 0) { s_cnt = 10; s_fast = 0; }
        }
    } else if (warp == 1) {
        const float* O = s_pose + NHAND*3;
        float p1x = (O[0]  + O[3]  + O[6]  + O[9] ) * 0.25f;
        float p1y = (O[1]  + O[4]  + O[7]  + O[10]) * 0.25f;
        float p1z = (O[2]  + O[5]  + O[8]  + O[11]) * 0.25f;
        float p2x = (O[12] + O[15] + O[18] + O[21]) * 0.25f;
        float p2y = (O[13] + O[16] + O[19] + O[22]) * 0.25f;
        float p2z = (O[14] + O[17] + O[20] + O[23]) * 0.25f;

        float dvx = p2x - p1x, dvy = p2y - p1y, dvz = p2z - p1z;
        float dvn = sqrtf(dvx*dvx + dvy*dvy + dvz*dvz);
        float dvn_e = dvn + 1e-5f;

        if (lane == 0) {
            s_geo[0] = p1x; s_geo[1] = p1y; s_geo[2] = p1z;
            s_geo[3] = dvx; s_geo[4] = dvy; s_geo[5] = dvz;
            s_geo[6] = dvx / dvn_e; s_geo[7] = dvy / dvn_e; s_geo[8] = dvz / dvn_e;
            s_geo[9] = dvn_e;
        }
    }
    __syncthreads();

    // ---- Phase D: one thread per contact; point rebuilt from bilinear coeffs ----
    if (tid < s_cnt) {
        float p1x = s_geo[0], p1y = s_geo[1], p1z = s_geo[2];
        float dvx = s_geo[3], dvy = s_geo[4], dvz = s_geo[5];
        float ndx = s_geo[6], ndy = s_geo[7], ndz = s_geo[8];
        float dvn_e = s_geo[9], thr = s_geo[10];

        int flat = s_self[tid];
        int h = flat / 6;
        int f = flat - h * 6;
        int p  = s_argp[flat];
        int iu = p / 11;
        int iv = p - iu * 11;
        float u = iu * 0.1f;
        float v = iv * 0.1f;
        const float* co = s_co + f*12;
        // P_d = a + u*b + v*(c + u*e)
        float cx = fmaf(v, fmaf(u, co[9],  co[6]),  fmaf(u, co[3], co[0]));
        float cy = fmaf(v, fmaf(u, co[10], co[7]),  fmaf(u, co[4], co[1]));
        float cz = fmaf(v, fmaf(u, co[11], co[8]),  fmaf(u, co[5], co[2]));
        float vx = cx - p1x, vy = cy - p1y, vz = cz - p1z;
        float inner = dvx*vx + dvy*vy + dvz*vz;
        float tt = inner / dvn_e;
        float rx = p1x + ndx * tt;
        float ry = p1y + ndy * tt;
        float rz = p1z + ndz * tt;
        float nx = cx - rx, ny = cy - ry, nz = cz - rz;
        float nn = sqrtf(nx*nx + ny*ny + nz*nz) + 1e-5f;
        nx /= nn; ny /= nn; nz /= nn;
        float m = 1.0f;
        if (!s_fast) {
            float dist = sqrtf(s_key[flat] + 1e-6f);
            m = (dist < thr) ? 1.0f : 0.0f;
        }
        s_cn[tid] = make_float4(m*nx, m*ny, m*nz, m);
    }
    __syncthreads();

    // ---- Per-batch result: |sum m n|^2 and (sum m)^2 ----
    if (tid < 32) {
        float sx = 0.0f, sy = 0.0f, sz = 0.0f, sc = 0.0f;
        if (tid < s_cnt) {
            float4 v = s_cn[tid];
            sx = v.x; sy = v.y; sz = v.z; sc = v.w;
        }
        #pragma unroll
        for (int off = 16; off; off >>= 1) {
            sx += __shfl_xor_sync(0xffffffffu, sx, off);
            sy += __shfl_xor_sync(0xffffffffu, sy, off);
            sz += __shfl_xor_sync(0xffffffffu, sz, off);
            sc += __shfl_xor_sync(0xffffffffu, sc, off);
        }
        if (tid == 0) {
            g_acc[b] = make_float2(sx*sx + sy*sy + sz*sz, sc*sc);
            __threadfence();                       // release g_acc[b]
            unsigned old = atomicAdd(&g_sem, 1u);
            s_flag = (old == (unsigned)(bs - 1));
        }
    }
    __syncthreads();

    // ---- Last block: deterministic final reduction, semaphore self-reset ----
    if (s_flag) {
        __threadfence();                           // acquire all g_acc
        float a = 0.0f, c = 0.0f;
        const float4* __restrict__ A = (const float4*)g_acc;
        int n4 = bs >> 1;
        for (int i = tid; i < n4; i += 128) {
            float4 v = A[i];
            a += v.x + v.z;
            c += v.y + v.w;
        }
        if ((bs & 1) && tid == 0) { float2 v = g_acc[bs - 1]; a += v.x; c += v.y; }
        #pragma unroll
        for (int off = 16; off; off >>= 1) {
            a += __shfl_xor_sync(0xffffffffu, a, off);
            c += __shfl_xor_sync(0xffffffffu, c, off);
        }
        if (lane == 0) s_red[warp] = make_float2(a, c);
        __syncthreads();
        if (tid == 0) {
            a = s_red[0].x + s_red[1].x + s_red[2].x + s_red[3].x;
            c = s_red[0].y + s_red[1].y + s_red[2].y + s_red[3].y;
            out[0] = a / (c + 1.0f);
            atomicExch(&g_sem, 0u);                // reset for next graph replay
        }
    }
}

extern "C" void kernel_launch(void* const* d_in, const int* in_sizes, int n_in,
                              void* d_out, int out_size)
{
    const float* poses = (const float*)d_in[0];
    int bs = in_sizes[0] / 87;
    if (bs > MAXB) bs = MAXB;
    affinity_main<<<bs, 128>>>(poses, (float*)d_out, bs);
}